// round 1
// baseline (speedup 1.0000x reference)
#include <cuda_runtime.h>
#include <math.h>

// Problem constants (fixed shapes from reference)
#define NFq   512    // fourier samples (n)
#define NSz   64     // noise size
#define HID   100    // hidden
#define FSz   256    // fourier feature size
#define Bq    32     // batch
#define Sq    1024   // seq len
#define Dq    3      // dsize
#define CH    4      // scan chunks
#define SCH   (Sq/CH)        // 256 s per chunk
#define NWPB  (NFq/32)       // 16 n-warps per batch
#define MUc   10.0f
// loglik2 = -MU*T*(2*pi)^(D-1) = -100 * (2pi)^2
#define LL2c  (-3947.8417604357434f)

// Device scratch (allocation-free rule: device globals)
__device__ float g_hidden[NFq*HID];
__device__ float g_fourier[NFq*FSz];
__device__ float g_womg[Dq*NFq];                 // [d][n]
__device__ float g_chunkC[Bq*CH*NFq];
__device__ float g_chunkS[Bq*CH*NFq];
__device__ __align__(16) float g_part[Bq*Sq*NWPB];  // per (b,s) 16 warp partials

// ---------------- Stage 1: tiny MLP -> Womg ----------------

__global__ void k_hidden(const float* __restrict__ noise,
                         const float* __restrict__ W1,
                         const float* __restrict__ b1) {
    int idx = blockIdx.x * blockDim.x + threadIdx.x;
    if (idx >= NFq * HID) return;
    int row = idx / HID, h = idx % HID;
    float acc = b1[h];
    const float* nr = noise + row * NSz;
#pragma unroll 8
    for (int k = 0; k < NSz; k++) acc = fmaf(nr[k], W1[k*HID + h], acc);
    g_hidden[row*HID + h] = tanhf(acc);
}

__global__ void k_fourier(const float* __restrict__ W2,
                          const float* __restrict__ b2) {
    int idx = blockIdx.x * blockDim.x + threadIdx.x;   // NFq*FSz threads
    int row = idx / FSz, j = idx % FSz;
    float acc = b2[j];
    const float* hr = g_hidden + row * HID;
#pragma unroll 5
    for (int h = 0; h < HID; h++) acc = fmaf(hr[h], W2[h*FSz + j], acc);
    g_fourier[row*FSz + j] = tanhf(acc);
}

__global__ void k_womg(const float* __restrict__ W) {
    int n = blockIdx.x * blockDim.x + threadIdx.x;
    if (n >= NFq) return;
    float a0 = 0.f, a1 = 0.f, a2 = 0.f;
    const float* fr = g_fourier + n * FSz;
#pragma unroll 4
    for (int j = 0; j < FSz; j++) {
        float f = fr[j];
        a0 = fmaf(f, W[j*Dq + 0], a0);
        a1 = fmaf(f, W[j*Dq + 1], a1);
        a2 = fmaf(f, W[j*Dq + 2], a2);
    }
    g_womg[0*NFq + n] = a0;
    g_womg[1*NFq + n] = a1;
    g_womg[2*NFq + n] = a2;
}

// ---------------- Stage 2: chunked scan ----------------
// Grid: Bq*16 blocks of 128 threads. blockIdx -> (b, chunk, ngroup).
// warp handles 32 consecutive n; lane owns one n; scans s in its chunk.

__global__ void k_passA(const float* __restrict__ X) {
    __shared__ float sx[SCH * 3];
    int bx = blockIdx.x;
    int b = bx >> 4;
    int r = bx & 15;
    int chunk = r >> 2;
    int ng = r & 3;
    const float* xp = X + (size_t)(b*Sq + chunk*SCH) * 3;
    for (int i = threadIdx.x; i < SCH*3; i += blockDim.x) sx[i] = xp[i];
    __syncthreads();

    int warp = threadIdx.x >> 5, lane = threadIdx.x & 31;
    int n = ng*128 + warp*32 + lane;
    float w0 = g_womg[n], w1 = g_womg[NFq + n], w2 = g_womg[2*NFq + n];
    float cC = 0.f, cS = 0.f;
#pragma unroll 4
    for (int s = 0; s < SCH; s++) {
        float x0 = sx[3*s], x1 = sx[3*s+1], x2 = sx[3*s+2];
        float th = fmaf(x2, w2, fmaf(x1, w1, x0 * w0));
        float sn, cs;
        __sincosf(th, &sn, &cs);
        cC += cs; cS += sn;
    }
    g_chunkC[(b*CH + chunk)*NFq + n] = cC;
    g_chunkS[(b*CH + chunk)*NFq + n] = cS;
}

__global__ void k_passB(const float* __restrict__ X) {
    __shared__ float sx[SCH * 3];
    int bx = blockIdx.x;
    int b = bx >> 4;
    int r = bx & 15;
    int chunk = r >> 2;
    int ng = r & 3;
    const float* xp = X + (size_t)(b*Sq + chunk*SCH) * 3;
    for (int i = threadIdx.x; i < SCH*3; i += blockDim.x) sx[i] = xp[i];
    __syncthreads();

    int warp = threadIdx.x >> 5, lane = threadIdx.x & 31;
    int n = ng*128 + warp*32 + lane;
    float w0 = g_womg[n], w1 = g_womg[NFq + n], w2 = g_womg[2*NFq + n];

    // exclusive carry from earlier chunks
    float cC = 0.f, cS = 0.f;
    for (int c = 0; c < chunk; c++) {
        cC += g_chunkC[(b*CH + c)*NFq + n];
        cS += g_chunkS[(b*CH + c)*NFq + n];
    }

    int widx = ng*4 + warp;                                 // 0..15
    float* part = g_part + (size_t)(b*Sq + chunk*SCH) * NWPB + widx;

#pragma unroll 4
    for (int s = 0; s < SCH; s++) {
        float x0 = sx[3*s], x1 = sx[3*s+1], x2 = sx[3*s+2];
        float th = fmaf(x2, w2, fmaf(x1, w1, x0 * w0));
        float sn, cs;
        __sincosf(th, &sn, &cs);
        float contrib = fmaf(cs, cC, sn * cS);   // uses EXCLUSIVE prefix
        cC += cs; cS += sn;
        contrib += __shfl_xor_sync(0xffffffffu, contrib, 16);
        contrib += __shfl_xor_sync(0xffffffffu, contrib, 8);
        contrib += __shfl_xor_sync(0xffffffffu, contrib, 4);
        contrib += __shfl_xor_sync(0xffffffffu, contrib, 2);
        contrib += __shfl_xor_sync(0xffffffffu, contrib, 1);
        if (lane == 0) part[(size_t)s * NWPB] = contrib;
    }
}

// ---------------- Stage 3: finalize ----------------

__global__ void k_final(const float* __restrict__ X,
                        const float* __restrict__ alpha,
                        float* __restrict__ out) {
    int i = blockIdx.x * blockDim.x + threadIdx.x;
    if (i >= Bq * Sq) return;
    int b = i / Sq, s = i % Sq;
    const float4* p = (const float4*)(g_part + (size_t)i * NWPB);
    float4 v0 = p[0], v1 = p[1], v2 = p[2], v3 = p[3];
    float ks = ((v0.x + v0.y) + (v0.z + v0.w))
             + ((v1.x + v1.y) + (v1.z + v1.w))
             + ((v2.x + v2.y) + (v2.z + v2.w))
             + ((v3.x + v3.y) + (v3.z + v3.w));
    float lam = fmaf(alpha[0], ks * (1.0f / NFq), MUc);
    out[i] = lam;                                         // lam [B,S]
    float mask = (X[(size_t)i * 3] > 0.f) ? 1.f : 0.f;
    float* ll = out + Bq*Sq;                              // loglik [B,S+1]
    ll[(size_t)b*(Sq+1) + s] = logf(lam) * mask + LL2c;
    if (s == 0) ll[(size_t)b*(Sq+1) + Sq] = LL2c;
}

// ---------------- Launch ----------------

extern "C" void kernel_launch(void* const* d_in, const int* in_sizes, int n_in,
                              void* d_out, int out_size) {
    const float* X     = (const float*)d_in[0];
    const float* noise = (const float*)d_in[1];
    const float* W1    = (const float*)d_in[2];
    const float* b1    = (const float*)d_in[3];
    const float* W2    = (const float*)d_in[4];
    const float* b2    = (const float*)d_in[5];
    const float* W     = (const float*)d_in[6];
    const float* alpha = (const float*)d_in[7];
    float* out = (float*)d_out;

    k_hidden<<<(NFq*HID + 255)/256, 256>>>(noise, W1, b1);
    k_fourier<<<(NFq*FSz)/256, 256>>>(W2, b2);
    k_womg<<<(NFq + 255)/256, 256>>>(W);
    k_passA<<<Bq*16, 128>>>(X);
    k_passB<<<Bq*16, 128>>>(X);
    k_final<<<(Bq*Sq)/256, 256>>>(X, alpha, out);
}

// round 4
// speedup vs baseline: 1.8882x; 1.8882x over previous
#include <cuda_runtime.h>
#include <math.h>

// Problem constants (fixed shapes)
#define NFq   512
#define NSz   64
#define HID   100
#define FSz   256
#define Bq    32
#define Sq    1024
#define Dq    3
#define CH    8              // scan chunks
#define SCH   (Sq/CH)        // 128 s per chunk
#define PSTR  65             // padded partial stride (conflict-free)
#define MUc   10.0f
#define LL2c  (-3947.8417604357434f)   // -MU*T*(2pi)^(D-1)

// Device scratch (allocation-free rule)
__device__ float g_womg[Dq*NFq];        // [d][n]
__device__ float g_chunkC[Bq*CH*NFq];
__device__ float g_chunkS[Bq*CH*NFq];

// ---------------- Stage 1: fused tiny MLP -> Womg ----------------
// One block per fourier row n (512 blocks, 128 threads).
__global__ void k_mlp(const float* __restrict__ noise,
                      const float* __restrict__ W1,
                      const float* __restrict__ b1,
                      const float* __restrict__ W2,
                      const float* __restrict__ b2,
                      const float* __restrict__ W) {
    __shared__ float snoise[NSz];
    __shared__ float shid[HID];
    __shared__ float sf[FSz];
    int n = blockIdx.x;
    int t = threadIdx.x;

    if (t < NSz) snoise[t] = noise[n*NSz + t];
    __syncthreads();

    if (t < HID) {
        float acc = b1[t];
#pragma unroll 8
        for (int k = 0; k < NSz; k++) acc = fmaf(snoise[k], W1[k*HID + t], acc);
        shid[t] = tanhf(acc);
    }
    __syncthreads();

    for (int j = t; j < FSz; j += 128) {
        float acc = b2[j];
#pragma unroll 4
        for (int h = 0; h < HID; h++) acc = fmaf(shid[h], W2[h*FSz + j], acc);
        sf[j] = tanhf(acc);
    }
    __syncthreads();

    int warp = t >> 5, lane = t & 31;
    if (warp < 3) {   // one warp per output dim d
        float acc = 0.f;
#pragma unroll 8
        for (int j = lane; j < FSz; j += 32) acc = fmaf(sf[j], W[j*Dq + warp], acc);
        acc += __shfl_xor_sync(0xffffffffu, acc, 16);
        acc += __shfl_xor_sync(0xffffffffu, acc, 8);
        acc += __shfl_xor_sync(0xffffffffu, acc, 4);
        acc += __shfl_xor_sync(0xffffffffu, acc, 2);
        acc += __shfl_xor_sync(0xffffffffu, acc, 1);
        if (lane == 0) g_womg[warp*NFq + n] = acc;
    }
}

// ---------------- Stage 2a: per-chunk sums (carries) ----------------
// Grid: Bq*(CH-1) blocks of 512 threads (last chunk's sums never used).
// Block covers all 512 n for one (b, chunk); lane owns one n.
__global__ void k_passA(const float* __restrict__ X) {
    __shared__ float4 sx[SCH];
    int b = blockIdx.x / (CH-1);
    int chunk = blockIdx.x % (CH-1);
    int tid = threadIdx.x;

    const float* xp = X + ((size_t)b*Sq + chunk*SCH) * 3;
    if (tid < SCH)
        sx[tid] = make_float4(xp[tid*3], xp[tid*3+1], xp[tid*3+2], 0.f);
    __syncthreads();

    int n = tid;  // warp*32+lane == tid for 512 threads
    float w0 = g_womg[n], w1 = g_womg[NFq + n], w2 = g_womg[2*NFq + n];
    float cC = 0.f, cS = 0.f;
#pragma unroll 4
    for (int s = 0; s < SCH; s++) {
        float4 x = sx[s];
        float th = fmaf(x.z, w2, fmaf(x.y, w1, x.x * w0));
        float sn, cs;
        __sincosf(th, &sn, &cs);
        cC += cs; cS += sn;
    }
    g_chunkC[(b*CH + chunk)*NFq + n] = cC;
    g_chunkS[(b*CH + chunk)*NFq + n] = cS;
}

// ---------------- Stage 2b: scan + reduce + finalize ----------------
// Grid: Bq*CH blocks of 512 threads. Writes lam and loglik directly.
__global__ void k_passB(const float* __restrict__ X,
                        const float* __restrict__ alpha,
                        float* __restrict__ out) {
    __shared__ float4 sx[SCH];
    __shared__ float part[SCH * PSTR];
    int b = blockIdx.x / CH;
    int chunk = blockIdx.x % CH;
    int tid = threadIdx.x;
    int warp = tid >> 5, lane = tid & 31;

    const float* xp = X + ((size_t)b*Sq + chunk*SCH) * 3;
    if (tid < SCH)
        sx[tid] = make_float4(xp[tid*3], xp[tid*3+1], xp[tid*3+2], 0.f);
    __syncthreads();

    int n = tid;
    float w0 = g_womg[n], w1 = g_womg[NFq + n], w2 = g_womg[2*NFq + n];

    // exclusive carry over earlier chunks (fixed ascending order: deterministic)
    float cC = 0.f, cS = 0.f;
    for (int c = 0; c < chunk; c++) {
        cC += g_chunkC[(b*CH + c)*NFq + n];
        cS += g_chunkS[(b*CH + c)*NFq + n];
    }

#pragma unroll 2
    for (int s = 0; s < SCH; s++) {
        float4 x = sx[s];
        float th = fmaf(x.z, w2, fmaf(x.y, w1, x.x * w0));
        float sn, cs;
        __sincosf(th, &sn, &cs);
        float contrib = fmaf(cs, cC, sn * cS);   // uses EXCLUSIVE prefix
        cC += cs; cS += sn;
        // truncated butterfly: lanes 0..3 end with 4 distinct partials (8 lanes each)
        contrib += __shfl_xor_sync(0xffffffffu, contrib, 16);
        contrib += __shfl_xor_sync(0xffffffffu, contrib, 8);
        contrib += __shfl_xor_sync(0xffffffffu, contrib, 4);
        if (lane < 4) part[s*PSTR + (warp << 2) + lane] = contrib;
    }
    __syncthreads();

    // epilogue: one thread per s sums 64 partials, writes lam + loglik
    if (tid < SCH) {
        float ks = 0.f;
        const float* pr = part + tid*PSTR;
#pragma unroll 16
        for (int j = 0; j < 64; j++) ks += pr[j];
        float lam = fmaf(alpha[0], ks * (1.0f / NFq), MUc);
        int s = chunk*SCH + tid;
        out[(size_t)b*Sq + s] = lam;                       // lam [B,S]
        float mask = (sx[tid].x > 0.f) ? 1.f : 0.f;
        out[Bq*Sq + (size_t)b*(Sq+1) + s] = logf(lam)*mask + LL2c;  // loglik [B,S+1]
    }
    if (chunk == 0 && tid == 0)
        out[Bq*Sq + (size_t)b*(Sq+1) + Sq] = LL2c;          // extra column
}

// ---------------- Launch ----------------
extern "C" void kernel_launch(void* const* d_in, const int* in_sizes, int n_in,
                              void* d_out, int out_size) {
    const float* X     = (const float*)d_in[0];
    const float* noise = (const float*)d_in[1];
    const float* W1    = (const float*)d_in[2];
    const float* b1    = (const float*)d_in[3];
    const float* W2    = (const float*)d_in[4];
    const float* b2    = (const float*)d_in[5];
    const float* W     = (const float*)d_in[6];
    const float* alpha = (const float*)d_in[7];
    float* out = (float*)d_out;

    k_mlp<<<NFq, 128>>>(noise, W1, b1, W2, b2, W);
    k_passA<<<Bq*(CH-1), 512>>>(X);
    k_passB<<<Bq*CH, 512>>>(X, alpha, out);
}

// round 6
// speedup vs baseline: 2.2750x; 1.2048x over previous
#include <cuda_runtime.h>
#include <math.h>

// Problem constants (fixed shapes)
#define NFq   512
#define NSz   64
#define HID   100
#define FSz   256
#define Bq    32
#define Sq    1024
#define Dq    3
#define CH    8              // scan chunks
#define SCH   (Sq/CH)        // 128 s per chunk
#define PSTR  68             // padded partial stride (16B-aligned rows)
#define MUc   10.0f
#define LL2c  (-3947.8417604357434f)   // -MU*T*(2pi)^(D-1)

// Device scratch (allocation-free rule)
__device__ float g_womg[Dq*NFq];        // [d][n]
__device__ float g_chunkC[Bq*CH*NFq];
__device__ float g_chunkS[Bq*CH*NFq];

// ---------------- Stage 1: fused tiny MLP -> Womg ----------------
// One block per fourier row n (512 blocks, 256 threads).
__global__ __launch_bounds__(256) void k_mlp(const float* __restrict__ noise,
                      const float* __restrict__ W1,
                      const float* __restrict__ b1,
                      const float* __restrict__ W2,
                      const float* __restrict__ b2,
                      const float* __restrict__ W) {
    __shared__ float snoise[NSz];
    __shared__ float shid[HID];
    __shared__ float sf[FSz];
    int n = blockIdx.x;
    int t = threadIdx.x;

    if (t < NSz) snoise[t] = noise[n*NSz + t];
    __syncthreads();

    if (t < HID) {
        float a0 = 0.f, a1 = 0.f, a2 = 0.f, a3 = 0.f;
#pragma unroll
        for (int k = 0; k < NSz; k += 4) {
            a0 = fmaf(snoise[k+0], W1[(k+0)*HID + t], a0);
            a1 = fmaf(snoise[k+1], W1[(k+1)*HID + t], a1);
            a2 = fmaf(snoise[k+2], W1[(k+2)*HID + t], a2);
            a3 = fmaf(snoise[k+3], W1[(k+3)*HID + t], a3);
        }
        shid[t] = tanhf(((a0+a1) + (a2+a3)) + b1[t]);
    }
    __syncthreads();

    {   // layer 2: one j per thread, 4-way accumulators (100 = 4*25)
        int j = t;
        float a0 = 0.f, a1 = 0.f, a2 = 0.f, a3 = 0.f;
#pragma unroll
        for (int h = 0; h < HID; h += 4) {
            a0 = fmaf(shid[h+0], W2[(h+0)*FSz + j], a0);
            a1 = fmaf(shid[h+1], W2[(h+1)*FSz + j], a1);
            a2 = fmaf(shid[h+2], W2[(h+2)*FSz + j], a2);
            a3 = fmaf(shid[h+3], W2[(h+3)*FSz + j], a3);
        }
        sf[j] = tanhf(((a0+a1) + (a2+a3)) + b2[j]);
    }
    __syncthreads();

    int warp = t >> 5, lane = t & 31;
    if (warp < 3) {   // one warp per output dim d
        float a0 = 0.f, a1 = 0.f;
#pragma unroll
        for (int j = 0; j < FSz; j += 64) {
            a0 = fmaf(sf[j + lane],      W[(j + lane)*Dq + warp],      a0);
            a1 = fmaf(sf[j + 32 + lane], W[(j + 32 + lane)*Dq + warp], a1);
        }
        float acc = a0 + a1;
        acc += __shfl_xor_sync(0xffffffffu, acc, 16);
        acc += __shfl_xor_sync(0xffffffffu, acc, 8);
        acc += __shfl_xor_sync(0xffffffffu, acc, 4);
        acc += __shfl_xor_sync(0xffffffffu, acc, 2);
        acc += __shfl_xor_sync(0xffffffffu, acc, 1);
        if (lane == 0) g_womg[warp*NFq + n] = acc;
    }
}

// ---------------- Stage 2a: per-chunk sums (carries) ----------------
// Grid: Bq*(CH-1) blocks of 512 threads (last chunk's sums never used).
__global__ void k_passA(const float* __restrict__ X) {
    __shared__ float4 sx[SCH];
    int b = blockIdx.x / (CH-1);
    int chunk = blockIdx.x % (CH-1);
    int tid = threadIdx.x;

    const float* xp = X + ((size_t)b*Sq + chunk*SCH) * 3;
    if (tid < SCH)
        sx[tid] = make_float4(xp[tid*3], xp[tid*3+1], xp[tid*3+2], 0.f);
    __syncthreads();

    int n = tid;
    float w0 = g_womg[n], w1 = g_womg[NFq + n], w2 = g_womg[2*NFq + n];
    float cC = 0.f, cS = 0.f;
#pragma unroll 4
    for (int s = 0; s < SCH; s++) {
        float4 x = sx[s];
        float th = fmaf(x.z, w2, fmaf(x.y, w1, x.x * w0));
        float sn, cs;
        __sincosf(th, &sn, &cs);
        cC += cs; cS += sn;
    }
    g_chunkC[(b*CH + chunk)*NFq + n] = cC;
    g_chunkS[(b*CH + chunk)*NFq + n] = cS;
}

// ---------------- Stage 2b: scan + reduce + finalize ----------------
// Grid: Bq*CH blocks of 512 threads. Writes lam and loglik directly.
__global__ void k_passB(const float* __restrict__ X,
                        const float* __restrict__ alpha,
                        float* __restrict__ out) {
    __shared__ float4 sx[SCH];
    __shared__ __align__(16) float part[SCH * PSTR];
    int b = blockIdx.x / CH;
    int chunk = blockIdx.x % CH;
    int tid = threadIdx.x;
    int warp = tid >> 5, lane = tid & 31;

    const float* xp = X + ((size_t)b*Sq + chunk*SCH) * 3;
    if (tid < SCH)
        sx[tid] = make_float4(xp[tid*3], xp[tid*3+1], xp[tid*3+2], 0.f);
    __syncthreads();

    int n = tid;
    float w0 = g_womg[n], w1 = g_womg[NFq + n], w2 = g_womg[2*NFq + n];

    // exclusive carry over earlier chunks (fixed ascending order: deterministic)
    float cC = 0.f, cS = 0.f;
    for (int c = 0; c < chunk; c++) {
        cC += g_chunkC[(b*CH + c)*NFq + n];
        cS += g_chunkS[(b*CH + c)*NFq + n];
    }

#pragma unroll 2
    for (int s = 0; s < SCH; s++) {
        float4 x = sx[s];
        float th = fmaf(x.z, w2, fmaf(x.y, w1, x.x * w0));
        float sn, cs;
        __sincosf(th, &sn, &cs);
        float contrib = fmaf(cs, cC, sn * cS);   // uses EXCLUSIVE prefix
        cC += cs; cS += sn;
        // truncated butterfly: lanes 0..3 end with 4 distinct partials (8 lanes each)
        contrib += __shfl_xor_sync(0xffffffffu, contrib, 16);
        contrib += __shfl_xor_sync(0xffffffffu, contrib, 8);
        contrib += __shfl_xor_sync(0xffffffffu, contrib, 4);
        if (lane < 4) part[s*PSTR + (warp << 2) + lane] = contrib;
    }
    __syncthreads();

    // epilogue: 4 threads per s, each sums 16 partials via 4x LDS.128
    {
        int s = tid >> 2;       // 0..127
        int q = tid & 3;        // quarter
        const float4* pr = (const float4*)(part + s*PSTR + q*16);
        float4 v0 = pr[0], v1 = pr[1], v2 = pr[2], v3 = pr[3];
        float ks = ((v0.x + v0.y) + (v0.z + v0.w))
                 + ((v1.x + v1.y) + (v1.z + v1.w))
                 + ((v2.x + v2.y) + (v2.z + v2.w))
                 + ((v3.x + v3.y) + (v3.z + v3.w));
        ks += __shfl_xor_sync(0xffffffffu, ks, 2);
        ks += __shfl_xor_sync(0xffffffffu, ks, 1);
        if (q == 0) {
            float lam = fmaf(alpha[0], ks * (1.0f / NFq), MUc);
            int sg = chunk*SCH + s;
            out[(size_t)b*Sq + sg] = lam;                      // lam [B,S]
            float mask = (sx[s].x > 0.f) ? 1.f : 0.f;
            out[Bq*Sq + (size_t)b*(Sq+1) + sg] = logf(lam)*mask + LL2c;  // loglik [B,S+1]
        }
    }
    if (chunk == 0 && tid == 0)
        out[Bq*Sq + (size_t)b*(Sq+1) + Sq] = LL2c;          // extra column
}

// ---------------- Launch ----------------
extern "C" void kernel_launch(void* const* d_in, const int* in_sizes, int n_in,
                              void* d_out, int out_size) {
    const float* X     = (const float*)d_in[0];
    const float* noise = (const float*)d_in[1];
    const float* W1    = (const float*)d_in[2];
    const float* b1    = (const float*)d_in[3];
    const float* W2    = (const float*)d_in[4];
    const float* b2    = (const float*)d_in[5];
    const float* W     = (const float*)d_in[6];
    const float* alpha = (const float*)d_in[7];
    float* out = (float*)d_out;

    k_mlp<<<NFq, 256>>>(noise, W1, b1, W2, b2, W);
    k_passA<<<Bq*(CH-1), 512>>>(X);
    k_passB<<<Bq*CH, 512>>>(X, alpha, out);
}